// round 4
// baseline (speedup 1.0000x reference)
#include <cuda_runtime.h>
#include <cstdint>

#define NB     16
#define NROWS  128
#define NT     128
#define NH     32
#define NG     96
#define NE     64
#define NVOCAB 258

// ---------------- static device scratch (no allocation allowed) ----------------
__device__ __align__(16) float  g_proj[NVOCAB * NG];        // embed @ Wih0^T        (99 KB)
__device__ __align__(16) float4 g_wpack[3 * 2 * 8 * NG];    // packed weights        (74 KB)
__device__ __align__(16) float  g_cbias[NG];                // b_ih0 + Wih0 @ b_h2e
__device__ __align__(16) float  g_w64[NG];                  // Wih0[:,64] (row feature col)
__device__ __align__(16) float2 g_wt2[32 * 129];            // w_out transposed pairs (33 KB)
__device__ __align__(16) float  g_gruout[NROWS * NT * NB * NH]; // top-layer GRU out (33.5 MB)
__device__ int g_flag[NROWS * 4];                           // progress per (row, batch-group)

// ---------------- small helpers ----------------
__device__ __forceinline__ int ld_acquire_gpu(const int* p) {
    int v;
    asm volatile("ld.acquire.gpu.s32 %0, [%1];" : "=r"(v) : "l"(p) : "memory");
    return v;
}
__device__ __forceinline__ void st_release_gpu(int* p, int v) {
    asm volatile("st.release.gpu.s32 [%0], %1;" :: "l"(p), "r"(v) : "memory");
}
__device__ __forceinline__ float sigf(float x) {
    return __fdividef(1.0f, 1.0f + __expf(-x));
}
__device__ __forceinline__ float tanhfast(float x) {
    return __fdividef(2.0f, 1.0f + __expf(-2.0f * x)) - 1.0f;
}

// ---------------- prep: build proj / Wc / cbias / wpack / wt2 ----------------
__global__ void prep_kernel(
    const float* __restrict__ embed,
    const float* __restrict__ wih0, const float* __restrict__ whh0,
    const float* __restrict__ wih1, const float* __restrict__ whh1,
    const float* __restrict__ wih2, const float* __restrict__ whh2,
    const float* __restrict__ w_h2e, const float* __restrict__ b_h2e,
    const float* __restrict__ bih0,
    const float* __restrict__ w_out)
{
    const int v = blockIdx.x;
    const int g = threadIdx.x;   // 0..95

    if (v < NVOCAB) {
        // proj[v][g] = sum_e embed[v][e] * wih0[g][e]   (e < 64)
        float s = 0.0f;
        #pragma unroll 8
        for (int e = 0; e < NE; ++e)
            s = fmaf(embed[v * NE + e], wih0[g * 65 + e], s);
        g_proj[v * NG + g] = s;
    } else if (v == NVOCAB) {
        // cbias, w64, Wc, and pack all weight matrices
        float cb = bih0[g];
        #pragma unroll 5
        for (int e = 0; e < 65; ++e)
            cb = fmaf(wih0[g * 65 + e], b_h2e[e], cb);
        g_cbias[g] = cb;
        g_w64[g] = wih0[g * 65 + 64];

        float wc[NH];
        #pragma unroll
        for (int k = 0; k < NH; ++k) {
            float s = 0.0f;
            for (int e = 0; e < 65; ++e)
                s = fmaf(wih0[g * 65 + e], w_h2e[e * NH + k], s);
            wc[k] = s;
        }
        #pragma unroll
        for (int c = 0; c < 8; ++c) {
            // layer 0: input side = Wc, hidden side = whh0
            g_wpack[((0 * 2 + 0) * 8 + c) * NG + g] =
                make_float4(wc[4 * c], wc[4 * c + 1], wc[4 * c + 2], wc[4 * c + 3]);
            g_wpack[((0 * 2 + 1) * 8 + c) * NG + g] =
                make_float4(whh0[g * 32 + 4 * c],     whh0[g * 32 + 4 * c + 1],
                            whh0[g * 32 + 4 * c + 2], whh0[g * 32 + 4 * c + 3]);
            // layer 1
            g_wpack[((1 * 2 + 0) * 8 + c) * NG + g] =
                make_float4(wih1[g * 32 + 4 * c],     wih1[g * 32 + 4 * c + 1],
                            wih1[g * 32 + 4 * c + 2], wih1[g * 32 + 4 * c + 3]);
            g_wpack[((1 * 2 + 1) * 8 + c) * NG + g] =
                make_float4(whh1[g * 32 + 4 * c],     whh1[g * 32 + 4 * c + 1],
                            whh1[g * 32 + 4 * c + 2], whh1[g * 32 + 4 * c + 3]);
            // layer 2
            g_wpack[((2 * 2 + 0) * 8 + c) * NG + g] =
                make_float4(wih2[g * 32 + 4 * c],     wih2[g * 32 + 4 * c + 1],
                            wih2[g * 32 + 4 * c + 2], wih2[g * 32 + 4 * c + 3]);
            g_wpack[((2 * 2 + 1) * 8 + c) * NG + g] =
                make_float4(whh2[g * 32 + 4 * c],     whh2[g * 32 + 4 * c + 1],
                            whh2[g * 32 + 4 * c + 2], whh2[g * 32 + 4 * c + 3]);
        }
    } else {
        // v == 259: w_out transposed vocab-pairs: wt2[k][p] = (w_out[2p][k], w_out[2p+1][k])
        for (int idx = g; idx < 32 * 129; idx += NG) {
            int k = idx / 129, p = idx % 129;
            g_wt2[idx] = make_float2(w_out[(2 * p) * NH + k], w_out[(2 * p + 1) * NH + k]);
        }
    }
}

__global__ void reset_kernel() {
    int i = threadIdx.x;
    if (i < NROWS * 4) g_flag[i] = 0;
}

// ---------------- GRU layer step (all 96 threads participate) ----------------
__device__ __forceinline__ void gru_layer(
    int g, int layer,
    const float (*__restrict__ in)[NH],   // [4][32] input vector (per batch)
    float (*__restrict__ h)[NH],          // [4][32] hidden, updated in place
    float* __restrict__ ai,               // [4] accum, pre-initialized with input-side bias
    float* __restrict__ ah,               // [4] accum, pre-initialized with hidden-side bias
    float (*__restrict__ gst)[NG])        // [4][96] gate staging
{
    const float4* __restrict__ wi = &g_wpack[(layer * 2 + 0) * 8 * NG + g];
    const float4* __restrict__ wh = &g_wpack[(layer * 2 + 1) * 8 * NG + g];
    #pragma unroll
    for (int c = 0; c < 8; ++c) {
        float4 wv = wi[c * NG];
        #pragma unroll
        for (int b = 0; b < 4; ++b) {
            float4 d = *reinterpret_cast<const float4*>(&in[b][c * 4]);
            ai[b] = fmaf(wv.w, d.w, fmaf(wv.z, d.z, fmaf(wv.y, d.y, fmaf(wv.x, d.x, ai[b]))));
        }
        float4 wv2 = wh[c * NG];
        #pragma unroll
        for (int b = 0; b < 4; ++b) {
            float4 d = *reinterpret_cast<const float4*>(&h[b][c * 4]);
            ah[b] = fmaf(wv2.w, d.w, fmaf(wv2.z, d.z, fmaf(wv2.y, d.y, fmaf(wv2.x, d.x, ah[b]))));
        }
    }
    // r gates (g<32) and z gates (32<=g<64): sigmoid(ai+ah)
    if (g < 64) {
        #pragma unroll
        for (int b = 0; b < 4; ++b) gst[b][g] = sigf(ai[b] + ah[b]);
    }
    __syncthreads();
    // n gates (g>=64): tanh(inn + r * hn)
    if (g >= 64) {
        #pragma unroll
        for (int b = 0; b < 4; ++b) gst[b][g] = tanhfast(fmaf(gst[b][g - 64], ah[b], ai[b]));
    }
    __syncthreads();
    // h' = (1-z)*n + z*h = n + z*(h-n)
    for (int idx = g; idx < 4 * NH; idx += NG) {
        int b = idx >> 5, j = idx & 31;
        float z = gst[b][32 + j], n = gst[b][64 + j];
        h[b][j] = fmaf(z, h[b][j] - n, n);
    }
    __syncthreads();
}

// ---------------- persistent wavefront RNN kernel ----------------
__global__ __launch_bounds__(96, 4) void rnn_kernel(
    const int* __restrict__ x,
    const float* __restrict__ bhh0,
    const float* __restrict__ bih1, const float* __restrict__ bhh1,
    const float* __restrict__ bih2, const float* __restrict__ bhh2)
{
    __shared__ __align__(16) float hsh[3][4][NH];
    __shared__ __align__(16) float prevsh[4][NH];
    __shared__ __align__(16) float gst[4][NG];
    __shared__ int toksh[4];

    const int tid = threadIdx.x;
    const int g   = tid;
    const int r   = blockIdx.x >> 2;
    const int grp = blockIdx.x & 3;
    const int b0  = grp * 4;

    for (int idx = tid; idx < 3 * 4 * NH; idx += NG)
        (&hsh[0][0][0])[idx] = 0.0f;

    const float rowfeat = (float)r * (2.0f / 128.0f) - 1.0f;
    const float cb  = g_cbias[g];
    const float w64 = g_w64[g];
    const float bh0 = bhh0[g];
    const float bi1 = bih1[g], bh1 = bhh1[g];
    const float bi2 = bih2[g], bh2 = bhh2[g];

    int*       myflag   = &g_flag[r * 4 + grp];
    const int* prevflag = &g_flag[(r - 1) * 4 + grp];

    __syncthreads();

    for (int t = 0; t < NT; ++t) {
        if (r > 0 && tid == 0) {
            while (ld_acquire_gpu(prevflag) <= t) { }
        }
        __syncthreads();

        if (tid < 4)
            toksh[tid] = x[(b0 + tid) * (NROWS * NT) + r * NT + t];
        if (r > 0) {
            const float* src = &g_gruout[(((r - 1) * NT + t) * NB) * NH];
            for (int idx = tid; idx < 4 * NH; idx += NG) {
                int bl = idx >> 5, j = idx & 31;
                prevsh[bl][j] = __ldcg(&src[(b0 + bl) * NH + j]);
            }
        } else {
            for (int idx = tid; idx < 4 * NH; idx += NG)
                (&prevsh[0][0])[idx] = 0.0f;
        }
        __syncthreads();

        float ai[4], ah[4];
        // layer 0: ai init = proj[token] + rowfeat*w64 + cbias ; ah init = b_hh0
        #pragma unroll
        for (int b = 0; b < 4; ++b) {
            ai[b] = g_proj[toksh[b] * NG + g] + fmaf(rowfeat, w64, cb);
            ah[b] = bh0;
        }
        gru_layer(g, 0, prevsh, hsh[0], ai, ah, gst);

        #pragma unroll
        for (int b = 0; b < 4; ++b) { ai[b] = bi1; ah[b] = bh1; }
        gru_layer(g, 1, hsh[0], hsh[1], ai, ah, gst);

        #pragma unroll
        for (int b = 0; b < 4; ++b) { ai[b] = bi2; ah[b] = bh2; }
        gru_layer(g, 2, hsh[1], hsh[2], ai, ah, gst);

        // emit top-layer output
        float* dst = &g_gruout[((r * NT + t) * NB) * NH];
        for (int idx = tid; idx < 4 * NH; idx += NG) {
            int bl = idx >> 5, j = idx & 31;
            dst[(b0 + bl) * NH + j] = hsh[2][bl][j];
        }
        __syncthreads();
        if (tid == 0) {
            __threadfence();
            st_release_gpu(myflag, t + 1);
        }
    }
}

// ---------------- epilogue: pred = out @ w_out^T + b_out (f32x2 packed) ----------------
__global__ __launch_bounds__(256) void out_kernel(
    float* __restrict__ outp, const float* __restrict__ b_out)
{
    __shared__ __align__(16) float hs[2][NH];
    const int tid = threadIdx.x;
    const long ciBase = (long)blockIdx.x * 2;

    if (tid < 64) {
        int c2 = tid >> 5, j = tid & 31;
        long ci = ciBase + c2;               // ci = b*16384 + r*128 + t
        int b  = (int)(ci >> 14);
        int rt = (int)(ci & 16383);
        hs[c2][j] = g_gruout[((long)rt * NB + b) * NH + j];
    }
    __syncthreads();

    const int c2 = tid >> 7;
    const int p  = tid & 127;                // vocab pair index (0..127); p==0 also does pair 128
    const long ci = ciBase + c2;
    const float* __restrict__ h = hs[c2];

    {
        float2 bo = reinterpret_cast<const float2*>(b_out)[p];
        unsigned long long acc;
        asm("mov.b64 %0, {%1, %2};" : "=l"(acc)
            : "r"(__float_as_uint(bo.x)), "r"(__float_as_uint(bo.y)));
        #pragma unroll
        for (int k = 0; k < NH; ++k) {
            unsigned int hb = __float_as_uint(h[k]);
            unsigned long long h2, w2;
            asm("mov.b64 %0, {%1, %1};" : "=l"(h2) : "r"(hb));
            w2 = *reinterpret_cast<const unsigned long long*>(&g_wt2[k * 129 + p]);
            asm("fma.rn.f32x2 %0, %1, %2, %3;" : "=l"(acc) : "l"(h2), "l"(w2), "l"(acc));
        }
        reinterpret_cast<unsigned long long*>(outp)[ci * 129 + p] = acc;
    }
    if (p == 0) {
        float2 bo = reinterpret_cast<const float2*>(b_out)[128];
        unsigned long long acc;
        asm("mov.b64 %0, {%1, %2};" : "=l"(acc)
            : "r"(__float_as_uint(bo.x)), "r"(__float_as_uint(bo.y)));
        #pragma unroll
        for (int k = 0; k < NH; ++k) {
            unsigned int hb = __float_as_uint(h[k]);
            unsigned long long h2, w2;
            asm("mov.b64 %0, {%1, %1};" : "=l"(h2) : "r"(hb));
            w2 = *reinterpret_cast<const unsigned long long*>(&g_wt2[k * 129 + 128]);
            asm("fma.rn.f32x2 %0, %1, %2, %3;" : "=l"(acc) : "l"(h2), "l"(w2), "l"(acc));
        }
        reinterpret_cast<unsigned long long*>(outp)[ci * 129 + 128] = acc;
    }
}

// ---------------- launch ----------------
extern "C" void kernel_launch(void* const* d_in, const int* in_sizes, int n_in,
                              void* d_out, int out_size)
{
    (void)in_sizes; (void)n_in; (void)out_size;
    const int*   x     = (const int*)  d_in[0];
    const float* embed = (const float*)d_in[1];
    const float* wih0  = (const float*)d_in[2];
    const float* whh0  = (const float*)d_in[3];
    const float* bih0  = (const float*)d_in[4];
    const float* bhh0  = (const float*)d_in[5];
    const float* wih1  = (const float*)d_in[6];
    const float* whh1  = (const float*)d_in[7];
    const float* bih1  = (const float*)d_in[8];
    const float* bhh1  = (const float*)d_in[9];
    const float* wih2  = (const float*)d_in[10];
    const float* whh2  = (const float*)d_in[11];
    const float* bih2  = (const float*)d_in[12];
    const float* bhh2  = (const float*)d_in[13];
    const float* w_h2e = (const float*)d_in[14];
    const float* b_h2e = (const float*)d_in[15];
    const float* w_out = (const float*)d_in[16];
    const float* b_out = (const float*)d_in[17];
    float* outp = (float*)d_out;

    prep_kernel<<<260, 96>>>(embed, wih0, whh0, wih1, whh1, wih2, whh2,
                             w_h2e, b_h2e, bih0, w_out);
    reset_kernel<<<1, 512>>>();
    rnn_kernel<<<NROWS * 4, 96>>>(x, bhh0, bih1, bhh1, bih2, bhh2);
    out_kernel<<<(NB * NROWS * NT) / 2, 256>>>(outp, b_out);
}

// round 5
// speedup vs baseline: 1.0116x; 1.0116x over previous
#include <cuda_runtime.h>
#include <cstdint>

#define NB     16
#define NROWS  128
#define NT     128
#define NH     32
#define NG     96
#define NE     64
#define NVOCAB 258

// ---------------- static device scratch (no allocation allowed) ----------------
__device__ __align__(16) float  g_proj[NVOCAB * NG];        // embed @ Wih0^T        (99 KB)
__device__ __align__(16) float4 g_wpack[3 * 2 * 8 * NG];    // packed weights        (74 KB)
__device__ __align__(16) float  g_cbias[NG];                // b_ih0 + Wih0 @ b_h2e
__device__ __align__(16) float  g_w64[NG];                  // Wih0[:,64] (row feature col)
__device__ __align__(16) float2 g_wt2[32 * 129];            // w_out transposed pairs (33 KB)
__device__ __align__(16) float  g_gruout[NROWS * NT * NB * NH]; // top-layer GRU out (33.5 MB)
__device__ int g_flag[NROWS * 4];                           // progress per (row, batch-group)

// ---------------- small helpers ----------------
__device__ __forceinline__ int ld_acquire_gpu(const int* p) {
    int v;
    asm volatile("ld.acquire.gpu.s32 %0, [%1];" : "=r"(v) : "l"(p) : "memory");
    return v;
}
__device__ __forceinline__ void st_release_gpu(int* p, int v) {
    asm volatile("st.release.gpu.s32 [%0], %1;" :: "l"(p), "r"(v) : "memory");
}
__device__ __forceinline__ float sigf(float x) {
    return __fdividef(1.0f, 1.0f + __expf(-x));
}
__device__ __forceinline__ float tanhfast(float x) {
    return __fdividef(2.0f, 1.0f + __expf(-2.0f * x)) - 1.0f;
}

// ---------------- prep: build proj / Wc / cbias / wpack / wt2 ----------------
__global__ void prep_kernel(
    const float* __restrict__ embed,
    const float* __restrict__ wih0, const float* __restrict__ whh0,
    const float* __restrict__ wih1, const float* __restrict__ whh1,
    const float* __restrict__ wih2, const float* __restrict__ whh2,
    const float* __restrict__ w_h2e, const float* __restrict__ b_h2e,
    const float* __restrict__ bih0,
    const float* __restrict__ w_out)
{
    const int v = blockIdx.x;
    const int g = threadIdx.x;   // 0..95

    if (v < NVOCAB) {
        // proj[v][g] = sum_e embed[v][e] * wih0[g][e]   (e < 64)
        float s = 0.0f;
        #pragma unroll 8
        for (int e = 0; e < NE; ++e)
            s = fmaf(embed[v * NE + e], wih0[g * 65 + e], s);
        g_proj[v * NG + g] = s;
    } else if (v == NVOCAB) {
        // cbias, w64, Wc, and pack all weight matrices
        float cb = bih0[g];
        #pragma unroll 5
        for (int e = 0; e < 65; ++e)
            cb = fmaf(wih0[g * 65 + e], b_h2e[e], cb);
        g_cbias[g] = cb;
        g_w64[g] = wih0[g * 65 + 64];

        float wc[NH];
        #pragma unroll
        for (int k = 0; k < NH; ++k) {
            float s = 0.0f;
            for (int e = 0; e < 65; ++e)
                s = fmaf(wih0[g * 65 + e], w_h2e[e * NH + k], s);
            wc[k] = s;
        }
        #pragma unroll
        for (int c = 0; c < 8; ++c) {
            // layer 0: input side = Wc, hidden side = whh0
            g_wpack[((0 * 2 + 0) * 8 + c) * NG + g] =
                make_float4(wc[4 * c], wc[4 * c + 1], wc[4 * c + 2], wc[4 * c + 3]);
            g_wpack[((0 * 2 + 1) * 8 + c) * NG + g] =
                make_float4(whh0[g * 32 + 4 * c],     whh0[g * 32 + 4 * c + 1],
                            whh0[g * 32 + 4 * c + 2], whh0[g * 32 + 4 * c + 3]);
            // layer 1
            g_wpack[((1 * 2 + 0) * 8 + c) * NG + g] =
                make_float4(wih1[g * 32 + 4 * c],     wih1[g * 32 + 4 * c + 1],
                            wih1[g * 32 + 4 * c + 2], wih1[g * 32 + 4 * c + 3]);
            g_wpack[((1 * 2 + 1) * 8 + c) * NG + g] =
                make_float4(whh1[g * 32 + 4 * c],     whh1[g * 32 + 4 * c + 1],
                            whh1[g * 32 + 4 * c + 2], whh1[g * 32 + 4 * c + 3]);
            // layer 2
            g_wpack[((2 * 2 + 0) * 8 + c) * NG + g] =
                make_float4(wih2[g * 32 + 4 * c],     wih2[g * 32 + 4 * c + 1],
                            wih2[g * 32 + 4 * c + 2], wih2[g * 32 + 4 * c + 3]);
            g_wpack[((2 * 2 + 1) * 8 + c) * NG + g] =
                make_float4(whh2[g * 32 + 4 * c],     whh2[g * 32 + 4 * c + 1],
                            whh2[g * 32 + 4 * c + 2], whh2[g * 32 + 4 * c + 3]);
        }
    } else {
        // v == 259: w_out transposed vocab-pairs: wt2[k][p] = (w_out[2p][k], w_out[2p+1][k])
        for (int idx = g; idx < 32 * 129; idx += NG) {
            int k = idx / 129, p = idx % 129;
            g_wt2[idx] = make_float2(w_out[(2 * p) * NH + k], w_out[(2 * p + 1) * NH + k]);
        }
    }
}

__global__ void reset_kernel() {
    int i = threadIdx.x;
    if (i < NROWS * 4) g_flag[i] = 0;
}

// ---------------- GRU layer step (all 96 threads participate) ----------------
__device__ __forceinline__ void gru_layer(
    int g, int layer,
    const float (*__restrict__ in)[NH],   // [4][32] input vector (per batch)
    float (*__restrict__ h)[NH],          // [4][32] hidden, updated in place
    float* __restrict__ ai,               // [4] accum, pre-initialized with input-side bias
    float* __restrict__ ah,               // [4] accum, pre-initialized with hidden-side bias
    float (*__restrict__ gst)[NG])        // [4][96] gate staging
{
    const float4* __restrict__ wi = &g_wpack[(layer * 2 + 0) * 8 * NG + g];
    const float4* __restrict__ wh = &g_wpack[(layer * 2 + 1) * 8 * NG + g];
    #pragma unroll
    for (int c = 0; c < 8; ++c) {
        float4 wv = wi[c * NG];
        #pragma unroll
        for (int b = 0; b < 4; ++b) {
            float4 d = *reinterpret_cast<const float4*>(&in[b][c * 4]);
            ai[b] = fmaf(wv.w, d.w, fmaf(wv.z, d.z, fmaf(wv.y, d.y, fmaf(wv.x, d.x, ai[b]))));
        }
        float4 wv2 = wh[c * NG];
        #pragma unroll
        for (int b = 0; b < 4; ++b) {
            float4 d = *reinterpret_cast<const float4*>(&h[b][c * 4]);
            ah[b] = fmaf(wv2.w, d.w, fmaf(wv2.z, d.z, fmaf(wv2.y, d.y, fmaf(wv2.x, d.x, ah[b]))));
        }
    }
    // r gates (g<32) and z gates (32<=g<64): sigmoid(ai+ah)
    if (g < 64) {
        #pragma unroll
        for (int b = 0; b < 4; ++b) gst[b][g] = sigf(ai[b] + ah[b]);
    }
    __syncthreads();
    // n gates (g>=64): tanh(inn + r * hn)
    if (g >= 64) {
        #pragma unroll
        for (int b = 0; b < 4; ++b) gst[b][g] = tanhfast(fmaf(gst[b][g - 64], ah[b], ai[b]));
    }
    __syncthreads();
    // h' = (1-z)*n + z*h = n + z*(h-n)
    for (int idx = g; idx < 4 * NH; idx += NG) {
        int b = idx >> 5, j = idx & 31;
        float z = gst[b][32 + j], n = gst[b][64 + j];
        h[b][j] = fmaf(z, h[b][j] - n, n);
    }
    __syncthreads();
}

// ---------------- persistent wavefront RNN kernel ----------------
__global__ __launch_bounds__(96, 4) void rnn_kernel(
    const int* __restrict__ x,
    const float* __restrict__ bhh0,
    const float* __restrict__ bih1, const float* __restrict__ bhh1,
    const float* __restrict__ bih2, const float* __restrict__ bhh2)
{
    __shared__ __align__(16) float hsh[3][4][NH];
    __shared__ __align__(16) float prevsh[4][NH];
    __shared__ __align__(16) float gst[4][NG];
    __shared__ int toksh[4];

    const int tid = threadIdx.x;
    const int g   = tid;
    const int r   = blockIdx.x >> 2;
    const int grp = blockIdx.x & 3;
    const int b0  = grp * 4;

    for (int idx = tid; idx < 3 * 4 * NH; idx += NG)
        (&hsh[0][0][0])[idx] = 0.0f;

    const float rowfeat = (float)r * (2.0f / 128.0f) - 1.0f;
    const float cb  = g_cbias[g];
    const float w64 = g_w64[g];
    const float bh0 = bhh0[g];
    const float bi1 = bih1[g], bh1 = bhh1[g];
    const float bi2 = bih2[g], bh2 = bhh2[g];

    int*       myflag   = &g_flag[r * 4 + grp];
    const int* prevflag = &g_flag[(r - 1) * 4 + grp];

    __syncthreads();

    for (int t = 0; t < NT; ++t) {
        if (r > 0 && tid == 0) {
            while (ld_acquire_gpu(prevflag) <= t) { }
        }
        __syncthreads();

        if (tid < 4)
            toksh[tid] = x[(b0 + tid) * (NROWS * NT) + r * NT + t];
        if (r > 0) {
            const float* src = &g_gruout[(((r - 1) * NT + t) * NB) * NH];
            for (int idx = tid; idx < 4 * NH; idx += NG) {
                int bl = idx >> 5, j = idx & 31;
                prevsh[bl][j] = __ldcg(&src[(b0 + bl) * NH + j]);
            }
        } else {
            for (int idx = tid; idx < 4 * NH; idx += NG)
                (&prevsh[0][0])[idx] = 0.0f;
        }
        __syncthreads();

        float ai[4], ah[4];
        // layer 0: ai init = proj[token] + rowfeat*w64 + cbias ; ah init = b_hh0
        #pragma unroll
        for (int b = 0; b < 4; ++b) {
            ai[b] = g_proj[toksh[b] * NG + g] + fmaf(rowfeat, w64, cb);
            ah[b] = bh0;
        }
        gru_layer(g, 0, prevsh, hsh[0], ai, ah, gst);

        #pragma unroll
        for (int b = 0; b < 4; ++b) { ai[b] = bi1; ah[b] = bh1; }
        gru_layer(g, 1, hsh[0], hsh[1], ai, ah, gst);

        #pragma unroll
        for (int b = 0; b < 4; ++b) { ai[b] = bi2; ah[b] = bh2; }
        gru_layer(g, 2, hsh[1], hsh[2], ai, ah, gst);

        // emit top-layer output
        float* dst = &g_gruout[((r * NT + t) * NB) * NH];
        for (int idx = tid; idx < 4 * NH; idx += NG) {
            int bl = idx >> 5, j = idx & 31;
            dst[(b0 + bl) * NH + j] = hsh[2][bl][j];
        }
        __syncthreads();
        if (tid == 0) {
            __threadfence();
            st_release_gpu(myflag, t + 1);
        }
    }
}

// ---------------- epilogue: pred = out @ w_out^T + b_out (f32x2 packed) ----------------
__global__ __launch_bounds__(256) void out_kernel(
    float* __restrict__ outp, const float* __restrict__ b_out)
{
    __shared__ __align__(16) float hs[2][NH];
    const int tid = threadIdx.x;
    const long ciBase = (long)blockIdx.x * 2;

    if (tid < 64) {
        int c2 = tid >> 5, j = tid & 31;
        long ci = ciBase + c2;               // ci = b*16384 + r*128 + t
        int b  = (int)(ci >> 14);
        int rt = (int)(ci & 16383);
        hs[c2][j] = g_gruout[((long)rt * NB + b) * NH + j];
    }
    __syncthreads();

    const int c2 = tid >> 7;
    const int p  = tid & 127;                // vocab pair index (0..127); p==0 also does pair 128
    const long ci = ciBase + c2;
    const float* __restrict__ h = hs[c2];

    {
        float2 bo = reinterpret_cast<const float2*>(b_out)[p];
        unsigned long long acc;
        asm("mov.b64 %0, {%1, %2};" : "=l"(acc)
            : "r"(__float_as_uint(bo.x)), "r"(__float_as_uint(bo.y)));
        #pragma unroll
        for (int k = 0; k < NH; ++k) {
            unsigned int hb = __float_as_uint(h[k]);
            unsigned long long h2, w2;
            asm("mov.b64 %0, {%1, %1};" : "=l"(h2) : "r"(hb));
            w2 = *reinterpret_cast<const unsigned long long*>(&g_wt2[k * 129 + p]);
            asm("fma.rn.f32x2 %0, %1, %2, %3;" : "=l"(acc) : "l"(h2), "l"(w2), "l"(acc));
        }
        reinterpret_cast<unsigned long long*>(outp)[ci * 129 + p] = acc;
    }
    if (p == 0) {
        float2 bo = reinterpret_cast<const float2*>(b_out)[128];
        unsigned long long acc;
        asm("mov.b64 %0, {%1, %2};" : "=l"(acc)
            : "r"(__float_as_uint(bo.x)), "r"(__float_as_uint(bo.y)));
        #pragma unroll
        for (int k = 0; k < NH; ++k) {
            unsigned int hb = __float_as_uint(h[k]);
            unsigned long long h2, w2;
            asm("mov.b64 %0, {%1, %1};" : "=l"(h2) : "r"(hb));
            w2 = *reinterpret_cast<const unsigned long long*>(&g_wt2[k * 129 + 128]);
            asm("fma.rn.f32x2 %0, %1, %2, %3;" : "=l"(acc) : "l"(h2), "l"(w2), "l"(acc));
        }
        reinterpret_cast<unsigned long long*>(outp)[ci * 129 + 128] = acc;
    }
}

// ---------------- launch ----------------
extern "C" void kernel_launch(void* const* d_in, const int* in_sizes, int n_in,
                              void* d_out, int out_size)
{
    (void)in_sizes; (void)n_in; (void)out_size;
    const int*   x     = (const int*)  d_in[0];
    const float* embed = (const float*)d_in[1];
    const float* wih0  = (const float*)d_in[2];
    const float* whh0  = (const float*)d_in[3];
    const float* bih0  = (const float*)d_in[4];
    const float* bhh0  = (const float*)d_in[5];
    const float* wih1  = (const float*)d_in[6];
    const float* whh1  = (const float*)d_in[7];
    const float* bih1  = (const float*)d_in[8];
    const float* bhh1  = (const float*)d_in[9];
    const float* wih2  = (const float*)d_in[10];
    const float* whh2  = (const float*)d_in[11];
    const float* bih2  = (const float*)d_in[12];
    const float* bhh2  = (const float*)d_in[13];
    const float* w_h2e = (const float*)d_in[14];
    const float* b_h2e = (const float*)d_in[15];
    const float* w_out = (const float*)d_in[16];
    const float* b_out = (const float*)d_in[17];
    float* outp = (float*)d_out;

    prep_kernel<<<260, 96>>>(embed, wih0, whh0, wih1, whh1, wih2, whh2,
                             w_h2e, b_h2e, bih0, w_out);
    reset_kernel<<<1, 512>>>();
    rnn_kernel<<<NROWS * 4, 96>>>(x, bhh0, bih1, bhh1, bih2, bhh2);
    out_kernel<<<(NB * NROWS * NT) / 2, 256>>>(outp, b_out);
}